// round 2
// baseline (speedup 1.0000x reference)
#include <cuda_runtime.h>
#include <cuda_bf16.h>
#include <cstdint>
#include <cstddef>

#define NN 16384
#define EE 524288
#define NF 256
#define NH 128

// ---------------- scratch (static device globals; no runtime alloc) ----------------
__device__ float g_t [NN * NH];
__device__ float g_b1[NN * NH];
__device__ float g_b2[NN * NH];
__device__ __nv_bfloat16 g_sb[NN * NH];
__device__ int   g_deg[NN];
__device__ int   g_rowptr[NN + 1];
__device__ int   g_cursor[NN];
__device__ int   g_col[EE];
__device__ float g_dinv[NN];
__device__ int   g_idx64;

// ---------------- helpers ----------------
__device__ __forceinline__ uint32_t smem_u32(const void* p) {
    uint32_t a;
    asm("{ .reg .u64 t; cvta.to.shared.u64 t, %1; cvt.u32.u64 %0, t; }" : "=r"(a) : "l"(p));
    return a;
}
__device__ __forceinline__ void ldmx4(uint32_t* r, uint32_t addr) {
    asm volatile("ldmatrix.sync.aligned.m8n8.x4.shared.b16 {%0,%1,%2,%3}, [%4];"
                 : "=r"(r[0]), "=r"(r[1]), "=r"(r[2]), "=r"(r[3]) : "r"(addr));
}
__device__ __forceinline__ void mma16816(float* c, const uint32_t* a,
                                         uint32_t b0, uint32_t b1) {
    asm volatile(
        "mma.sync.aligned.m16n8k16.row.col.f32.bf16.bf16.f32 "
        "{%0,%1,%2,%3}, {%4,%5,%6,%7}, {%8,%9}, {%0,%1,%2,%3};"
        : "+f"(c[0]), "+f"(c[1]), "+f"(c[2]), "+f"(c[3])
        : "r"(a[0]), "r"(a[1]), "r"(a[2]), "r"(a[3]), "r"(b0), "r"(b1));
}

// ---------------- preprocessing kernels ----------------
__global__ void detect_k(const int* __restrict__ ei) {
    int t = threadIdx.x;                 // 128 threads
    int v = ei[2 * t + 1];               // high word if int64 layout
    int ok = __syncthreads_and(v == 0);
    if (t == 0) g_idx64 = ok ? 1 : 0;
}
__global__ void zero_k() {
    int i = blockIdx.x * blockDim.x + threadIdx.x;
    if (i < NN) g_deg[i] = 0;
}
__global__ void degree_k(const int* __restrict__ ei) {
    int e = blockIdx.x * blockDim.x + threadIdx.x;
    if (e >= EE) return;
    int d = g_idx64 ? ei[2 * (EE + e)] : ei[EE + e];
    atomicAdd(&g_deg[d], 1);
}
__global__ void dinv_k() {
    int i = blockIdx.x * blockDim.x + threadIdx.x;
    if (i < NN) g_dinv[i] = rsqrtf((float)g_deg[i] + 1.0f);
}
__global__ void scan_k() {
    __shared__ int sums[1024];
    int t = threadIdx.x;
    int base = t * 16;
    int local[16];
    int s = 0;
#pragma unroll
    for (int i = 0; i < 16; i++) { local[i] = s; s += g_deg[base + i]; }
    sums[t] = s;
    __syncthreads();
    for (int off = 1; off < 1024; off <<= 1) {
        int v = (t >= off) ? sums[t - off] : 0;
        __syncthreads();
        sums[t] += v;
        __syncthreads();
    }
    int pre = (t > 0) ? sums[t - 1] : 0;
#pragma unroll
    for (int i = 0; i < 16; i++) g_rowptr[base + i] = pre + local[i];
    if (t == 1023) g_rowptr[NN] = sums[1023];
}
__global__ void copycur_k() {
    int i = blockIdx.x * blockDim.x + threadIdx.x;
    if (i < NN) g_cursor[i] = g_rowptr[i];
}
__global__ void scatter_k(const int* __restrict__ ei) {
    int e = blockIdx.x * blockDim.x + threadIdx.x;
    if (e >= EE) return;
    int s, d;
    if (g_idx64) { s = ei[2 * e]; d = ei[2 * (EE + e)]; }
    else         { s = ei[e];     d = ei[EE + e]; }
    int p = atomicAdd(&g_cursor[d], 1);
    g_col[p] = s;
}

// ---------------- dense fp32 SGEMM: C[M,N] = A[M,K] @ B[K,N] (+bias, relu) ----------------
__global__ void __launch_bounds__(256) sgemm_k(const float* __restrict__ A,
                                               const float* __restrict__ B,
                                               const float* __restrict__ bias,
                                               float* __restrict__ C,
                                               int M, int K, int N, int doBiasRelu) {
    __shared__ float As[16][136];
    __shared__ float Bs[16][128];
    int tid = threadIdx.x;
    int tx = tid & 15, ty = tid >> 4;
    int m0 = blockIdx.x * 128, n0 = blockIdx.y * 128;
    float acc[8][8];
#pragma unroll
    for (int i = 0; i < 8; i++)
#pragma unroll
        for (int j = 0; j < 8; j++) acc[i][j] = 0.0f;

    for (int k0 = 0; k0 < K; k0 += 16) {
#pragma unroll
        for (int i = 0; i < 8; i++) {
            int idx = tid + i * 256;
            int r = idx >> 4, c = idx & 15;
            As[c][r] = A[(size_t)(m0 + r) * K + k0 + c];
        }
#pragma unroll
        for (int i = 0; i < 8; i++) {
            int idx = tid + i * 256;
            int r = idx >> 7, c = idx & 127;
            Bs[r][c] = B[(size_t)(k0 + r) * N + n0 + c];
        }
        __syncthreads();
#pragma unroll
        for (int kk = 0; kk < 16; kk++) {
            float ra[8], rb[8];
            *(float4*)&ra[0] = *(float4*)&As[kk][ty * 4];
            *(float4*)&ra[4] = *(float4*)&As[kk][64 + ty * 4];
            *(float4*)&rb[0] = *(float4*)&Bs[kk][tx * 4];
            *(float4*)&rb[4] = *(float4*)&Bs[kk][64 + tx * 4];
#pragma unroll
            for (int i = 0; i < 8; i++)
#pragma unroll
                for (int j = 0; j < 8; j++) acc[i][j] += ra[i] * rb[j];
        }
        __syncthreads();
    }
#pragma unroll
    for (int i = 0; i < 8; i++) {
        int r = m0 + ((i < 4) ? (ty * 4 + i) : (64 + ty * 4 + i - 4));
#pragma unroll
        for (int h = 0; h < 2; h++) {
            int c = n0 + (h ? (64 + tx * 4) : (tx * 4));
            float4 v = make_float4(acc[i][h * 4 + 0], acc[i][h * 4 + 1],
                                   acc[i][h * 4 + 2], acc[i][h * 4 + 3]);
            if (doBiasRelu) {
                float4 b = *(const float4*)&bias[c];
                v.x = fmaxf(v.x + b.x, 0.0f);
                v.y = fmaxf(v.y + b.y, 0.0f);
                v.z = fmaxf(v.z + b.z, 0.0f);
                v.w = fmaxf(v.w + b.w, 0.0f);
            }
            *(float4*)&C[(size_t)r * N + c] = v;
        }
    }
}

// ---------------- SpMM: out = P @ T (128-wide), optional +bias & relu ----------------
__global__ void __launch_bounds__(256) spmm_k(const float* __restrict__ T,
                                              const float* __restrict__ bias,
                                              float* __restrict__ out,
                                              int doBiasRelu) {
    int gw = (blockIdx.x * blockDim.x + threadIdx.x) >> 5;
    int lane = threadIdx.x & 31;
    if (gw >= NN) return;
    int i = gw;
    float di = g_dinv[i];
    float4 ts = ((const float4*)(T + (size_t)i * NH))[lane];
    float4 acc;
    acc.x = di * ts.x; acc.y = di * ts.y; acc.z = di * ts.z; acc.w = di * ts.w;
    int e0 = g_rowptr[i], e1 = g_rowptr[i + 1];
#pragma unroll 2
    for (int e = e0; e < e1; e++) {
        int j = g_col[e];
        float w = g_dinv[j];
        float4 tv = ((const float4*)(T + (size_t)j * NH))[lane];
        acc.x += w * tv.x; acc.y += w * tv.y; acc.z += w * tv.z; acc.w += w * tv.w;
    }
    float4 r;
    r.x = di * acc.x; r.y = di * acc.y; r.z = di * acc.z; r.w = di * acc.w;
    if (doBiasRelu) {
        float4 b = ((const float4*)bias)[lane];
        r.x = fmaxf(r.x + b.x, 0.0f);
        r.y = fmaxf(r.y + b.y, 0.0f);
        r.z = fmaxf(r.z + b.z, 0.0f);
        r.w = fmaxf(r.w + b.w, 0.0f);
    }
    ((float4*)(out + (size_t)i * NH))[lane] = r;
}

__global__ void cvt_k(const float* __restrict__ src) {
    int i = blockIdx.x * blockDim.x + threadIdx.x;
    if (i < NN * NH) g_sb[i] = __float2bfloat16(src[i]);
}

// ---------------- A_hat = S @ S^T via ldmatrix + mma.sync (bf16, fp32 accum) ----------
// CTA tile 128(M) x 256(N), K = 128 fully in smem. 512 threads = 16 warps (4m x 4n),
// warp tile 32 x 64. Rows padded to 136 bf16 (272B = 17 x 16B, odd -> ldmatrix
// conflict-free).
#define APAD 136
#define A_BYTES (128 * APAD * 2)
#define B_BYTES (256 * APAD * 2)
#define AH_SMEM (A_BYTES + B_BYTES)

__global__ void __launch_bounds__(512, 1) ahat_k(const __nv_bfloat16* __restrict__ S,
                                                 float* __restrict__ out) {
    extern __shared__ char smem[];
    uint32_t abase = smem_u32(smem);
    uint32_t bbase = abase + A_BYTES;
    int tid = threadIdx.x, lane = tid & 31, wid = tid >> 5;
    int wm = wid & 3, wn = wid >> 2;

    int m0 = (blockIdx.x >> 6) * 128;
    int n0 = (blockIdx.x & 63) * 256;

    // ---- fill smem (16B chunks; rows of 128 bf16 = 16 chunks) ----
#pragma unroll
    for (int i = 0; i < 4; i++) {                 // A: 2048 chunks / 512 thr
        int idx = tid + i * 512;
        int r = idx >> 4, c8 = (idx & 15) << 3;
        uint4 v = *(const uint4*)(S + (size_t)(m0 + r) * NH + c8);
        *(uint4*)(smem + (size_t)(r * APAD + c8) * 2) = v;
    }
#pragma unroll
    for (int i = 0; i < 8; i++) {                 // B: 4096 chunks
        int idx = tid + i * 512;
        int r = idx >> 4, c8 = (idx & 15) << 3;
        uint4 v = *(const uint4*)(S + (size_t)(n0 + r) * NH + c8);
        *(uint4*)(smem + A_BYTES + (size_t)(r * APAD + c8) * 2) = v;
    }
    __syncthreads();

    // ---- lane-dependent ldmatrix base addresses ----
    // A x4: matrices {rows0-7 klo, rows8-15 klo, rows0-7 khi, rows8-15 khi}
    uint32_t aAddr = abase +
        (uint32_t)(((wm * 32 + (lane & 15)) * APAD + ((lane >> 1) & 8)) * 2);
    // B x4: matrices {nt0 klo, nt0 khi, nt1 klo, nt1 khi}
    uint32_t bAddr = bbase +
        (uint32_t)(((wn * 64 + (lane & 7) + ((lane >> 4) << 3)) * APAD + (lane & 8)) * 2);

    float c[2][8][4];
#pragma unroll
    for (int mt = 0; mt < 2; mt++)
#pragma unroll
        for (int nt = 0; nt < 8; nt++)
#pragma unroll
            for (int q = 0; q < 4; q++) c[mt][nt][q] = 0.0f;

#pragma unroll
    for (int k = 0; k < 8; k++) {                 // 8 k-steps of 16
        uint32_t a[2][4];
        ldmx4(a[0], aAddr + k * 32);
        ldmx4(a[1], aAddr + 16 * (APAD * 2) + k * 32);
        uint32_t b[4][4];
#pragma unroll
        for (int p = 0; p < 4; p++)
            ldmx4(b[p], bAddr + p * 16 * (APAD * 2) + k * 32);
#pragma unroll
        for (int mt = 0; mt < 2; mt++)
#pragma unroll
            for (int p = 0; p < 4; p++) {
                mma16816(c[mt][2 * p + 0], a[mt], b[p][0], b[p][1]);
                mma16816(c[mt][2 * p + 1], a[mt], b[p][2], b[p][3]);
            }
    }

    // ---- epilogue: direct float2 stores ----
    int r0 = m0 + wm * 32 + (lane >> 2);
    int cb = n0 + wn * 64 + 2 * (lane & 3);
#pragma unroll
    for (int mt = 0; mt < 2; mt++) {
        int row = r0 + mt * 16;
#pragma unroll
        for (int nt = 0; nt < 8; nt++) {
            int col = cb + nt * 8;
            *(float2*)(out + (size_t)row * NN + col) =
                make_float2(c[mt][nt][0], c[mt][nt][1]);
            *(float2*)(out + (size_t)(row + 8) * NN + col) =
                make_float2(c[mt][nt][2], c[mt][nt][3]);
        }
    }
}

// ---------------- launch ----------------
extern "C" void kernel_launch(void* const* d_in, const int* in_sizes, int n_in,
                              void* d_out, int out_size) {
    const float* x   = (const float*)d_in[0];
    const int*   ei  = (const int*)d_in[1];
    const float* We1 = (const float*)d_in[2];
    const float* be1 = (const float*)d_in[3];
    const float* We2 = (const float*)d_in[4];
    const float* be2 = (const float*)d_in[5];
    const float* Wa1 = (const float*)d_in[6];
    const float* ba1 = (const float*)d_in[7];
    const float* Wa2 = (const float*)d_in[8];
    const float* ba2 = (const float*)d_in[9];
    const float* Ws1 = (const float*)d_in[10];
    const float* bs1 = (const float*)d_in[11];

    float* Ahat = (float*)d_out;
    float* Xhat = (float*)d_out + (size_t)NN * NN;

    float *t, *b1, *b2;
    __nv_bfloat16* sb;
    cudaGetSymbolAddress((void**)&t,  g_t);
    cudaGetSymbolAddress((void**)&b1, g_b1);
    cudaGetSymbolAddress((void**)&b2, g_b2);
    cudaGetSymbolAddress((void**)&sb, g_sb);

    // ---- CSR preprocessing ----
    detect_k<<<1, 128>>>(ei);
    zero_k<<<64, 256>>>();
    degree_k<<<EE / 256, 256>>>(ei);
    dinv_k<<<64, 256>>>();
    scan_k<<<1, 1024>>>();
    copycur_k<<<64, 256>>>();
    scatter_k<<<EE / 256, 256>>>(ei);

    // ---- encoder ----
    sgemm_k<<<dim3(128, 1), 256>>>(x, We1, nullptr, t, NN, NF, NH, 0);
    spmm_k<<<2048, 256>>>(t, be1, b1, 1);                       // z1
    sgemm_k<<<dim3(128, 1), 256>>>(b1, We2, nullptr, t, NN, NH, NH, 0);
    spmm_k<<<2048, 256>>>(t, be2, b2, 1);                       // z2 (kept)

    // ---- attribute decoder ----
    sgemm_k<<<dim3(128, 1), 256>>>(b2, Wa1, nullptr, t, NN, NH, NH, 0);
    spmm_k<<<2048, 256>>>(t, ba1, b1, 1);                       // a
    spmm_k<<<2048, 256>>>(b1, nullptr, t, 0);                   // u = P @ a
    sgemm_k<<<dim3(128, 2), 256>>>(t, Wa2, ba2, Xhat, NN, NH, NF, 1);  // X_hat

    // ---- structure decoder ----
    sgemm_k<<<dim3(128, 1), 256>>>(b2, Ws1, nullptr, t, NN, NH, NH, 0);
    spmm_k<<<2048, 256>>>(t, bs1, b1, 1);                       // s
    cvt_k<<<(NN * NH) / 256, 256>>>(b1);

    cudaFuncSetAttribute(ahat_k, cudaFuncAttributeMaxDynamicSharedMemorySize, AH_SMEM);
    ahat_k<<<128 * 64, 512, AH_SMEM>>>(sb, Ahat);
}